// round 2
// baseline (speedup 1.0000x reference)
#include <cuda_runtime.h>

#define THRESH 0.3f
#define MARGIN 0.1f
#define WEIGHT 0.1f

#define NBLK 1184
#define NTHR 256

__device__ float g_partial_sum[NBLK];
__device__ int   g_partial_cnt[NBLK];
__device__ unsigned int g_done = 0;

__device__ __forceinline__ void proc_row(float p4, float p5, float p6, float t,
                                         float& s, int& c) {
    bool b = p5 > THRESH;
    bool m45  = (p4 > THRESH) && b;
    bool m56  = b && (p6 > THRESH);
    bool m456 = m45 && (p6 > THRESH);
    float d45 = p5 - p4;
    float d56 = p6 - p5;
    float t45 = fmaxf(MARGIN - t * d45, 0.0f);
    float t56 = fmaxf(MARGIN - t * d56, 0.0f);
    float tor = fmaxf(fabsf(d45) - fabsf(d56) + MARGIN, 0.0f);
    if (m45)  { s += t45; c++; }
    if (m56)  { s += t56; c++; }
    if (m456) { s += tor; c++; }
}

__device__ __forceinline__ void proc_group(const float4* __restrict__ pred,
                                           const float4* __restrict__ t4,
                                           int g, float& s, int& c) {
    float4 tt = t4[g];
    float4 p0 = pred[4 * g + 0];
    float4 p1 = pred[4 * g + 1];
    float4 p2 = pred[4 * g + 2];
    float4 p3 = pred[4 * g + 3];
    proc_row(p0.y, p0.z, p0.w, tt.x, s, c);
    proc_row(p1.y, p1.z, p1.w, tt.y, s, c);
    proc_row(p2.y, p2.z, p2.w, tt.z, s, c);
    proc_row(p3.y, p3.z, p3.w, tt.w, s, c);
}

__global__ __launch_bounds__(NTHR) void loss_fused_kernel(
    const float4* __restrict__ pred,   // [B,4] as float4 per row
    const float4* __restrict__ t4,     // [B] viewed as float4 (B % 4 == 0)
    int ngroups,                       // B / 4
    float* __restrict__ out)
{
    float s = 0.0f;
    int   c = 0;
    const int stride = NBLK * NTHR;
    int g = blockIdx.x * NTHR + threadIdx.x;

    // unroll-2 grid-stride: 10 LDG.128 in flight per iteration
    for (; g + stride < ngroups; g += 2 * stride) {
        proc_group(pred, t4, g,          s, c);
        proc_group(pred, t4, g + stride, s, c);
    }
    if (g < ngroups) proc_group(pred, t4, g, s, c);

    // ---- block reduce ----
    #pragma unroll
    for (int o = 16; o > 0; o >>= 1) {
        s += __shfl_down_sync(0xFFFFFFFFu, s, o);
        c += __shfl_down_sync(0xFFFFFFFFu, c, o);
    }
    __shared__ float ws[NTHR / 32];
    __shared__ int   wc[NTHR / 32];
    __shared__ bool  amLast;
    int lane = threadIdx.x & 31;
    int wid  = threadIdx.x >> 5;
    if (lane == 0) { ws[wid] = s; wc[wid] = c; }
    __syncthreads();
    if (wid == 0) {
        s = (lane < NTHR / 32) ? ws[lane] : 0.0f;
        c = (lane < NTHR / 32) ? wc[lane] : 0;
        #pragma unroll
        for (int o = 4; o > 0; o >>= 1) {
            s += __shfl_down_sync(0xFFFFFFFFu, s, o);
            c += __shfl_down_sync(0xFFFFFFFFu, c, o);
        }
        if (lane == 0) {
            g_partial_sum[blockIdx.x] = s;
            g_partial_cnt[blockIdx.x] = c;
            __threadfence();
            unsigned int old = atomicAdd(&g_done, 1u);
            amLast = (old == NBLK - 1);
        }
    }
    __syncthreads();

    // ---- last block finalizes (deterministic fixed-order sum) ----
    if (amLast) {
        float fs = 0.0f;
        int   fc = 0;
        for (int i = threadIdx.x; i < NBLK; i += NTHR) {
            fs += g_partial_sum[i];
            fc += g_partial_cnt[i];
        }
        #pragma unroll
        for (int o = 16; o > 0; o >>= 1) {
            fs += __shfl_down_sync(0xFFFFFFFFu, fs, o);
            fc += __shfl_down_sync(0xFFFFFFFFu, fc, o);
        }
        __shared__ float fws[NTHR / 32];
        __shared__ int   fwc[NTHR / 32];
        if (lane == 0) { fws[wid] = fs; fwc[wid] = fc; }
        __syncthreads();
        if (wid == 0) {
            fs = (lane < NTHR / 32) ? fws[lane] : 0.0f;
            fc = (lane < NTHR / 32) ? fwc[lane] : 0;
            #pragma unroll
            for (int o = 4; o > 0; o >>= 1) {
                fs += __shfl_down_sync(0xFFFFFFFFu, fs, o);
                fc += __shfl_down_sync(0xFFFFFFFFu, fc, o);
            }
            if (lane == 0) {
                float loss = (fc > 0) ? (fs / fmaxf((float)fc, 1.0f)) : fs;
                out[0] = WEIGHT * loss;
                g_done = 0;          // reset for next graph replay
                __threadfence();
            }
        }
    }
}

extern "C" void kernel_launch(void* const* d_in, const int* in_sizes, int n_in,
                              void* d_out, int out_size)
{
    const float4* pred = (const float4*)d_in[0];     // predictions [B,4]
    const float4* t4   = (const float4*)d_in[1];     // relative_times [B,1]
    int B = in_sizes[1];
    int ngroups = B / 4;

    loss_fused_kernel<<<NBLK, NTHR>>>(pred, t4, ngroups, (float*)d_out);
}

// round 3
// speedup vs baseline: 1.1981x; 1.1981x over previous
#include <cuda_runtime.h>

#define THRESH 0.3f
#define MARGIN 0.1f
#define WEIGHT 0.1f

#define NBLK 1184
#define NTHR 256

__device__ float g_partial_sum[NBLK];
__device__ int   g_partial_cnt[NBLK];
__device__ unsigned int g_done = 0;

__device__ __forceinline__ void proc_row(float p4, float p5, float p6, float t,
                                         float& s, int& c) {
    bool b = p5 > THRESH;
    bool m45  = (p4 > THRESH) && b;
    bool m56  = b && (p6 > THRESH);
    bool m456 = m45 && (p6 > THRESH);
    float d45 = p5 - p4;
    float d56 = p6 - p5;
    float t45 = fmaxf(MARGIN - t * d45, 0.0f);
    float t56 = fmaxf(MARGIN - t * d56, 0.0f);
    float tor = fmaxf(fabsf(d45) - fabsf(d56) + MARGIN, 0.0f);
    if (m45)  { s += t45; c++; }
    if (m56)  { s += t56; c++; }
    if (m456) { s += tor; c++; }
}

__global__ __launch_bounds__(NTHR, 8) void loss_fused_kernel(
    const float4* __restrict__ pred,   // [B,4]: one float4 per row
    const float*  __restrict__ times,  // [B]
    int B,
    float* __restrict__ out)
{
    float s = 0.0f;
    int   c = 0;
    const int stride = NBLK * NTHR;
    int i = blockIdx.x * NTHR + threadIdx.x;

    // dense-per-instruction accesses: lanes contiguous in both arrays
    for (; i + stride < B; i += 2 * stride) {
        float4 pa = pred[i];
        float  ta = times[i];
        float4 pb = pred[i + stride];
        float  tb = times[i + stride];
        proc_row(pa.y, pa.z, pa.w, ta, s, c);
        proc_row(pb.y, pb.z, pb.w, tb, s, c);
    }
    if (i < B) {
        float4 pa = pred[i];
        float  ta = times[i];
        proc_row(pa.y, pa.z, pa.w, ta, s, c);
    }

    // ---- block reduce ----
    #pragma unroll
    for (int o = 16; o > 0; o >>= 1) {
        s += __shfl_down_sync(0xFFFFFFFFu, s, o);
        c += __shfl_down_sync(0xFFFFFFFFu, c, o);
    }
    __shared__ float ws[NTHR / 32];
    __shared__ int   wc[NTHR / 32];
    __shared__ bool  amLast;
    int lane = threadIdx.x & 31;
    int wid  = threadIdx.x >> 5;
    if (lane == 0) { ws[wid] = s; wc[wid] = c; }
    __syncthreads();
    if (wid == 0) {
        s = (lane < NTHR / 32) ? ws[lane] : 0.0f;
        c = (lane < NTHR / 32) ? wc[lane] : 0;
        #pragma unroll
        for (int o = 4; o > 0; o >>= 1) {
            s += __shfl_down_sync(0xFFFFFFFFu, s, o);
            c += __shfl_down_sync(0xFFFFFFFFu, c, o);
        }
        if (lane == 0) {
            g_partial_sum[blockIdx.x] = s;
            g_partial_cnt[blockIdx.x] = c;
            __threadfence();
            unsigned int old = atomicAdd(&g_done, 1u);
            amLast = (old == NBLK - 1);
        }
    }
    __syncthreads();

    // ---- last block finalizes (deterministic fixed-order sum) ----
    if (amLast) {
        float fs = 0.0f;
        int   fc = 0;
        for (int k = threadIdx.x; k < NBLK; k += NTHR) {
            fs += g_partial_sum[k];
            fc += g_partial_cnt[k];
        }
        #pragma unroll
        for (int o = 16; o > 0; o >>= 1) {
            fs += __shfl_down_sync(0xFFFFFFFFu, fs, o);
            fc += __shfl_down_sync(0xFFFFFFFFu, fc, o);
        }
        __shared__ float fws[NTHR / 32];
        __shared__ int   fwc[NTHR / 32];
        if (lane == 0) { fws[wid] = fs; fwc[wid] = fc; }
        __syncthreads();
        if (wid == 0) {
            fs = (lane < NTHR / 32) ? fws[lane] : 0.0f;
            fc = (lane < NTHR / 32) ? fwc[lane] : 0;
            #pragma unroll
            for (int o = 4; o > 0; o >>= 1) {
                fs += __shfl_down_sync(0xFFFFFFFFu, fs, o);
                fc += __shfl_down_sync(0xFFFFFFFFu, fc, o);
            }
            if (lane == 0) {
                float loss = (fc > 0) ? (fs / fmaxf((float)fc, 1.0f)) : fs;
                out[0] = WEIGHT * loss;
                g_done = 0;          // reset for next graph replay
                __threadfence();
            }
        }
    }
}

extern "C" void kernel_launch(void* const* d_in, const int* in_sizes, int n_in,
                              void* d_out, int out_size)
{
    const float4* pred  = (const float4*)d_in[0];   // predictions [B,4]
    const float*  times = (const float*)d_in[1];    // relative_times [B,1]
    int B = in_sizes[1];

    loss_fused_kernel<<<NBLK, NTHR>>>(pred, times, B, (float*)d_out);
}